// round 11
// baseline (speedup 1.0000x reference)
#include <cuda_runtime.h>
#include <math_constants.h>
#include <math.h>

#define NUM_VIEW 300
#define NPAIR    150   // view pairs
#define WVIEW    80    // window: views scanned per point (covering-radius bound)
#define W0MAX    (NUM_VIEW - WVIEW)   // 220
#define TPB      896   // threads per block (4 lanes/point)

// Codebook passed BY VALUE as a kernel parameter (2.4KB, constant bank).
// Pair j (views 2j, 2j+1):  A[j] = bits of {x0, x1, y0, y1}
// z is analytic (z_i = (2i+1)/300 - 1) and the -|v|^2/2 term is an
// argmax-invariant constant (up to ~1e-7), so only x,y are stored.
struct NPCodebook {
    ulonglong2 A[NPAIR];
};

__device__ __forceinline__ unsigned long long np_fma2(
        unsigned long long a, unsigned long long b, unsigned long long c) {
    unsigned long long d;
    asm("fma.rn.f32x2 %0, %1, %2, %3;" : "=l"(d) : "l"(a), "l"(b), "l"(c));
    return d;
}

__device__ __forceinline__ unsigned long long np_add2(
        unsigned long long a, unsigned long long b) {
    unsigned long long d;
    asm("add.rn.f32x2 %0, %1, %2;" : "=l"(d) : "l"(a), "l"(b));
    return d;
}

__device__ __forceinline__ unsigned long long np_pack2(float lo, float hi) {
    unsigned long long d;
    asm("mov.b64 %0, {%1, %2};" : "=l"(d) : "f"(lo), "f"(hi));
    return d;
}

__device__ __forceinline__ void np_unpack2(float& lo, float& hi,
                                           unsigned long long v) {
    asm("mov.b64 {%0, %1}, %2;" : "=f"(lo), "=f"(hi) : "l"(v));
}

__device__ __forceinline__ void np_merge_max(float& s0, int& i0, float s1, int i1) {
    // first-max (lowest index) wins on ties — matches argmin-first semantics
    bool g = (s1 > s0) || (s1 == s0 && i1 < i0);
    s0 = g ? s1 : s0;
    i0 = g ? i1 : i0;
}

// 4 threads per point. Views sorted by z -> winner lies within +-40 indices
// of i_c = round((u_z+1)*150). Lane h scans window pairs with
// (j - jp) mod 4 == h: jA = jp+h+8m, jB = jA+4, m=0..4 (10 pairs = 20 views).
// Codebook xy: kernel param -> smem; z-term analytic in packed registers.
// argmin(|n-v|^2) == argmax(dot(n,v)) up to argmax-invariant eps.
// MODE 0: indices written as float32 (output = 13*P floats)
// MODE 1: indices written as int64 bit-pattern (output = 14*P float slots)
template <int MODE>
__global__ void __launch_bounds__(TPB)
np_main_kernel(const __grid_constant__ NPCodebook cb,
               const float* __restrict__ normals,
               const int*   __restrict__ idxs,
               float*       __restrict__ out,
               int N, int S, int logS, int P) {
    __shared__ ulonglong2 sA[NPAIR];

    int tid = threadIdx.x;
    int t   = blockIdx.x * TPB + tid;
    int p   = t >> 2;
    int h   = t & 3;
    int pc  = (p < P) ? p : (P - 1);  // clamp, keep barrier convergent

    // gather loads issued first — the long chain we're hiding with warps
    int b   = (logS >= 0) ? (pc >> logS) : (pc / S);
    int idx = idxs[pc];
    const float* nptr = normals + ((long long)b * N + idx) * 3;
    float nx = __ldg(nptr + 0);
    float ny = __ldg(nptr + 1);
    float nz = __ldg(nptr + 2);

    // codebook param (constant bank) -> shared
    for (int i = tid; i < NPAIR; i += TPB)
        sA[i] = cb.A[i];
    __syncthreads();

    // window center from normalized z (approximation fine: 1.4x margin)
    float nn  = fmaf(nx, nx, fmaf(ny, ny, nz * nz));
    float uz  = nz * rsqrtf(nn);
    int   ic  = __float2int_rn(fmaf(uz, 150.0f, 150.0f));
    int   w0  = ic - (WVIEW / 2);
    w0 = (w0 < 0) ? 0 : ((w0 > W0MAX) ? W0MAX : w0);
    w0 &= ~1;                 // even start so pairs align
    int jp = w0 >> 1;         // first window pair

    unsigned long long pnx = np_pack2(nx, nx);
    unsigned long long pny = np_pack2(ny, ny);

    // analytic z-terms: pair j holds views 2j (lo), 2j+1 (hi);
    // z_lo(j) = (4j+1)/300 - 1, z_hi = z_lo + 2/300.
    // jA(m) = jp + h + 8m  -> dz per m = 32/300; jB = jA + 4 -> +16/300.
    const float inv300 = 1.0f / 300.0f;
    int jA0 = jp + h;
    float zAlo = fmaf((float)(4 * jA0 + 1), inv300, -1.0f);
    float zAhi = zAlo + 2.0f * inv300;
    unsigned long long pzA = np_pack2(nz * zAlo, nz * zAhi);
    float zoffB = nz * (16.0f * inv300);
    unsigned long long pzB = np_add2(pzA, np_pack2(zoffB, zoffB));
    float dzf = nz * (32.0f * inv300);
    unsigned long long dpz = np_pack2(dzf, dzf);

    // --- argmax over this lane's 10 window pairs: 2 pairs/iter, 5 iters ---
    float bAl = -CUDART_INF_F, bAh = -CUDART_INF_F,
          bBl = -CUDART_INF_F, bBh = -CUDART_INF_F;
    int   mAl = 0, mAh = 0, mBl = 0, mBh = 0;

#pragma unroll
    for (int m = 0; m < 5; m++) {
        int jA = jp + h + 8 * m;
        int jB = jA + 4;
        ulonglong2 A0 = sA[jA];
        ulonglong2 A1 = sA[jB];

        unsigned long long s0 = np_fma2(pnx, A0.x, np_fma2(pny, A0.y, pzA));
        unsigned long long s1 = np_fma2(pnx, A1.x, np_fma2(pny, A1.y, pzB));
        pzA = np_add2(pzA, dpz);
        pzB = np_add2(pzB, dpz);

        float f0l, f0h, f1l, f1h;
        np_unpack2(f0l, f0h, s0);
        np_unpack2(f1l, f1h, s1);

        // strict > keeps first-win; ternary form -> SEL (4-cyc) chains
        bool gAl = f0l > bAl;  bAl = gAl ? f0l : bAl;  mAl = gAl ? m : mAl;
        bool gAh = f0h > bAh;  bAh = gAh ? f0h : bAh;  mAh = gAh ? m : mAh;
        bool gBl = f1l > bBl;  bBl = gBl ? f1l : bBl;  mBl = gBl ? m : mBl;
        bool gBh = f1h > bBh;  bBh = gBh ? f1h : bBh;  mBh = gBh ? m : mBh;
    }

    // reconstruct global view indices
    int iAl = 2 * (jp + h + 8 * mAl);
    int iAh = 2 * (jp + h + 8 * mAh) + 1;
    int iBl = 2 * (jp + h + 8 * mBl + 4);
    int iBh = 2 * (jp + h + 8 * mBh + 4) + 1;

    // merge 4 accumulators (index tie-break keeps exact first-win semantics)
    np_merge_max(bAl, iAl, bAh, iAh);
    np_merge_max(bBl, iBl, bBh, iBh);
    np_merge_max(bAl, iAl, bBl, iBl);

    // butterfly merge across the 4 lanes of the point
    float os; int oi;
    os = __shfl_xor_sync(0xffffffffu, bAl, 1);
    oi = __shfl_xor_sync(0xffffffffu, iAl, 1);
    np_merge_max(bAl, iAl, os, oi);
    os = __shfl_xor_sync(0xffffffffu, bAl, 2);
    oi = __shfl_xor_sync(0xffffffffu, iAl, 2);
    np_merge_max(bAl, iAl, os, oi);
    int bi = iAl;

    // --- rotation matrix from towards = -n, angle = 0 (R1 = I, rot = R2) ---
    float ax_x = -nx, ax_y = -ny, ax_z = -nz;
    float ay_x = -ax_y;   // = ny
    float ay_y =  ax_x;   // = -nx
    float ay_z = 0.0f;
    if (ay_x * ay_x + ay_y * ay_y + ay_z * ay_z == 0.0f) {
        ay_x = 0.0f; ay_y = 1.0f; ay_z = 0.0f;
    }
    float inva = 1.0f / sqrtf(ax_x * ax_x + ax_y * ax_y + ax_z * ax_z);
    ax_x *= inva; ax_y *= inva; ax_z *= inva;
    float invy = 1.0f / sqrtf(ay_x * ay_x + ay_y * ay_y + ay_z * ay_z);
    ay_x *= invy; ay_y *= invy; ay_z *= invy;
    float az_x = ax_y * ay_z - ax_z * ay_y;
    float az_y = ax_z * ay_x - ax_x * ay_z;
    float az_z = ax_x * ay_y - ax_y * ay_x;

    // --- outputs (stores split between the four lanes of the point) ---
    if (p < P) {
        float* out_xyz;
        float* out_rot;
        if (MODE == 0) {
            out_xyz = out + P;
            out_rot = out + P + 3 * (long long)P;
        } else {
            out_xyz = out + 2 * (long long)P;
            out_rot = out + 2 * (long long)P + 3 * (long long)P;
        }

        long long base3 = (long long)p * 3;
        long long base9 = (long long)p * 9;

        // row-major [r][c]: col0 = ax, col1 = ay, col2 = az
        if (h == 0) {
            if (MODE == 0) {
                out[p] = (float)bi;
            } else {
                ((long long*)out)[p] = (long long)bi;
            }
            out_xyz[base3 + 0] = nx;
            out_xyz[base3 + 1] = ny;
        } else if (h == 1) {
            out_xyz[base3 + 2] = nz;
            out_rot[base9 + 0] = ax_x;
            out_rot[base9 + 1] = ay_x;
            out_rot[base9 + 2] = az_x;
        } else if (h == 2) {
            out_rot[base9 + 3] = ax_y;
            out_rot[base9 + 4] = ay_y;
            out_rot[base9 + 5] = az_y;
        } else {
            out_rot[base9 + 6] = ax_z;
            out_rot[base9 + 7] = ay_z;
            out_rot[base9 + 8] = az_z;
        }
    }
}

// Host-side codebook build (fp64 libm matches numpy's float64 path).
static void np_build_codebook(NPCodebook* cb) {
    const double PHI = (sqrt(5.0) - 1.0) * 0.5;
    for (int i = 0; i < NUM_VIEW; i++) {
        double di = (double)i;
        double zi = (2.0 * di + 1.0) / (double)NUM_VIEW - 1.0;
        double r2 = 1.0 - zi * zi;
        if (r2 < 0.0) r2 = 0.0;
        double r  = sqrt(r2);
        double ang = 2.0 * di * M_PI * PHI;
        float xf = (float)(r * cos(ang));
        float yf = (float)(r * sin(ang));

        int j = i >> 1;
        int o = i & 1;
        float* fa = (float*)&cb->A[j];
        fa[0 + o] = xf;
        fa[2 + o] = yf;
    }
}

extern "C" void kernel_launch(void* const* d_in, const int* in_sizes, int n_in,
                              void* d_out, int out_size) {
    const float* normals = (const float*)d_in[0];
    const int*   idxs    = (const int*)d_in[1];
    float*       out     = (float*)d_out;

    const int B = 8;
    int P = in_sizes[1];            // B*S = 32768
    int S = P / B;                  // 4096
    int N = in_sizes[0] / (B * 3);  // 500000

    int logS = -1;
    if (S > 0 && (S & (S - 1)) == 0) {
        logS = 0;
        while ((1 << logS) < S) logS++;
    }

    NPCodebook cb;
    np_build_codebook(&cb);

    // 4 lanes per point; single kernel: 147 blocks x 896 threads
    long long total = 4LL * P;
    int blocks = (int)((total + TPB - 1) / TPB);
    if (out_size == 14 * P) {
        np_main_kernel<1><<<blocks, TPB>>>(cb, normals, idxs, out, N, S, logS, P);
    } else {
        np_main_kernel<0><<<blocks, TPB>>>(cb, normals, idxs, out, N, S, logS, P);
    }
}

// round 12
// speedup vs baseline: 1.0037x; 1.0037x over previous
#include <cuda_runtime.h>
#include <math_constants.h>
#include <math.h>

#define NUM_VIEW 300
#define NPAIR    150   // view pairs
#define WVIEW    80    // window: views scanned per point (covering-radius bound)
#define W0MAX    (NUM_VIEW - WVIEW)   // 220
#define TPB      448   // threads per block (2 lanes/point)
#define NWARPS   (TPB / 32)           // 14
#define PPW      16    // points per warp

// Codebook passed BY VALUE as a kernel parameter (2.4KB, constant bank).
// Pair j (views 2j, 2j+1):  A[j] = bits of {x0, x1, y0, y1}
// z is analytic (z_i = (2i+1)/300 - 1) and the -|v|^2/2 term is an
// argmax-invariant constant (up to ~1e-7), so only x,y are stored.
struct NPCodebook {
    ulonglong2 A[NPAIR];
};

__device__ __forceinline__ unsigned long long np_fma2(
        unsigned long long a, unsigned long long b, unsigned long long c) {
    unsigned long long d;
    asm("fma.rn.f32x2 %0, %1, %2, %3;" : "=l"(d) : "l"(a), "l"(b), "l"(c));
    return d;
}

__device__ __forceinline__ unsigned long long np_add2(
        unsigned long long a, unsigned long long b) {
    unsigned long long d;
    asm("add.rn.f32x2 %0, %1, %2;" : "=l"(d) : "l"(a), "l"(b));
    return d;
}

__device__ __forceinline__ unsigned long long np_pack2(float lo, float hi) {
    unsigned long long d;
    asm("mov.b64 %0, {%1, %2};" : "=l"(d) : "f"(lo), "f"(hi));
    return d;
}

__device__ __forceinline__ void np_unpack2(float& lo, float& hi,
                                           unsigned long long v) {
    asm("mov.b64 {%0, %1}, %2;" : "=f"(lo), "=f"(hi) : "l"(v));
}

__device__ __forceinline__ void np_merge_max(float& s0, int& i0, float s1, int i1) {
    // first-max (lowest index) wins on ties — matches argmin-first semantics
    bool g = (s1 > s0) || (s1 == s0 && i1 < i0);
    s0 = g ? s1 : s0;
    i0 = g ? i1 : i0;
}

// 2 threads per point. Views sorted by z -> winner lies within +-40 indices
// of i_c = round((u_z+1)*150). Codebook xy: kernel param -> smem (2.4KB);
// z-term carried analytically in packed registers.
// Epilogue: warp-staged in smem, then fully coalesced float4 copy-out
// (no block barrier — __syncwarp only).
// MODE 0: indices written as float32 (output = 13*P floats)
// MODE 1: indices written as int64 bit-pattern (output = 14*P float slots)
template <int MODE>
__global__ void __launch_bounds__(TPB)
np_main_kernel(const __grid_constant__ NPCodebook cb,
               const float* __restrict__ normals,
               const int*   __restrict__ idxs,
               float*       __restrict__ out,
               int N, int S, int logS, int P) {
    __shared__ ulonglong2 sA[NPAIR];
    __shared__ __align__(16) float sROT[NWARPS * PPW * 9];   // 576B/warp
    __shared__ __align__(16) float sXYZ[NWARPS * PPW * 3];   // 192B/warp
    __shared__ __align__(16) unsigned long long sIND[NWARPS * PPW]; // 128B/warp

    int tid  = threadIdx.x;
    int lane = tid & 31;
    int w    = tid >> 5;
    int lp   = lane >> 1;             // local point in warp (0..15)
    int t    = blockIdx.x * TPB + tid;
    int p    = t >> 1;
    int h    = t & 1;
    int pc   = (p < P) ? p : (P - 1); // clamp, keep barrier convergent

    // gather loads issued first — overlap with codebook preload
    int b   = (logS >= 0) ? (pc >> logS) : (pc / S);
    int idx = idxs[pc];
    const float* nptr = normals + ((long long)b * N + idx) * 3;
    float nx = __ldg(nptr + 0);
    float ny = __ldg(nptr + 1);
    float nz = __ldg(nptr + 2);

    // codebook param (constant bank) -> shared
    for (int i = tid; i < NPAIR; i += TPB)
        sA[i] = cb.A[i];
    __syncthreads();

    // window center from normalized z (approximation fine: 1.4x margin)
    float nn  = fmaf(nx, nx, fmaf(ny, ny, nz * nz));
    float uz  = nz * rsqrtf(nn);
    int   ic  = __float2int_rn(fmaf(uz, 150.0f, 150.0f));
    int   w0  = ic - (WVIEW / 2);
    w0 = (w0 < 0) ? 0 : ((w0 > W0MAX) ? W0MAX : w0);
    w0 &= ~1;                 // even start so pairs align
    int jp = w0 >> 1;         // first window pair

    unsigned long long pnx = np_pack2(nx, nx);
    unsigned long long pny = np_pack2(ny, ny);

    // analytic z-terms: pair j holds views 2j (lo), 2j+1 (hi);
    // z_lo(j) = (4j+1)/300 - 1, z_hi = z_lo + 2/300.
    // jA(m) = jp + 2m + h -> dz per m = 16/300; jB = jA + 20 -> +80/300.
    const float inv300 = 1.0f / 300.0f;
    int jA0 = jp + h;
    float zAlo = fmaf((float)(4 * jA0 + 1), inv300, -1.0f);
    float zAhi = zAlo + 2.0f * inv300;
    unsigned long long pzA = np_pack2(nz * zAlo, nz * zAhi);
    float zstep = nz * (80.0f * inv300);
    unsigned long long pzB = np_add2(pzA, np_pack2(zstep, zstep));
    float dzf = nz * (8.0f * inv300);
    unsigned long long dpz = np_pack2(dzf, dzf);

    // --- argmax over this lane's 20 window pairs: 2 pairs/iter, 10 iters ---
    float bAl = -CUDART_INF_F, bAh = -CUDART_INF_F,
          bBl = -CUDART_INF_F, bBh = -CUDART_INF_F;
    int   mAl = 0, mAh = 0, mBl = 0, mBh = 0;

#pragma unroll
    for (int m = 0; m < 10; m++) {
        int jA = jp + 2 * m + h;
        int jB = jA + 20;
        ulonglong2 A0 = sA[jA];
        ulonglong2 A1 = sA[jB];

        unsigned long long s0 = np_fma2(pnx, A0.x, np_fma2(pny, A0.y, pzA));
        unsigned long long s1 = np_fma2(pnx, A1.x, np_fma2(pny, A1.y, pzB));
        pzA = np_add2(pzA, dpz);
        pzB = np_add2(pzB, dpz);

        float f0l, f0h, f1l, f1h;
        np_unpack2(f0l, f0h, s0);
        np_unpack2(f1l, f1h, s1);

        // strict > keeps first-win; ternary form -> SEL (4-cyc) chains
        bool gAl = f0l > bAl;  bAl = gAl ? f0l : bAl;  mAl = gAl ? m : mAl;
        bool gAh = f0h > bAh;  bAh = gAh ? f0h : bAh;  mAh = gAh ? m : mAh;
        bool gBl = f1l > bBl;  bBl = gBl ? f1l : bBl;  mBl = gBl ? m : mBl;
        bool gBh = f1h > bBh;  bBh = gBh ? f1h : bBh;  mBh = gBh ? m : mBh;
    }

    // reconstruct global view indices
    int iAl = 2 * (jp + 2 * mAl + h);
    int iAh = 2 * (jp + 2 * mAh + h) + 1;
    int iBl = 2 * (jp + 2 * mBl + h + 20);
    int iBh = 2 * (jp + 2 * mBh + h + 20) + 1;

    // merge 4 accumulators (index tie-break keeps exact first-win semantics)
    np_merge_max(bAl, iAl, bAh, iAh);
    np_merge_max(bBl, iBl, bBh, iBh);
    np_merge_max(bAl, iAl, bBl, iBl);

    // merge across the lane pair
    float os = __shfl_xor_sync(0xffffffffu, bAl, 1);
    int   oi = __shfl_xor_sync(0xffffffffu, iAl, 1);
    np_merge_max(bAl, iAl, os, oi);
    int bi = iAl;

    // --- rotation matrix from towards = -n, angle = 0 (R1 = I, rot = R2) ---
    float ax_x = -nx, ax_y = -ny, ax_z = -nz;
    float ay_x = -ax_y;   // = ny
    float ay_y =  ax_x;   // = -nx
    float ay_z = 0.0f;
    if (ay_x * ay_x + ay_y * ay_y + ay_z * ay_z == 0.0f) {
        ay_x = 0.0f; ay_y = 1.0f; ay_z = 0.0f;
    }
    float inva = 1.0f / sqrtf(ax_x * ax_x + ax_y * ax_y + ax_z * ax_z);
    ax_x *= inva; ax_y *= inva; ax_z *= inva;
    float invy = 1.0f / sqrtf(ay_x * ay_x + ay_y * ay_y + ay_z * ay_z);
    ay_x *= invy; ay_y *= invy; ay_z *= invy;
    float az_x = ax_y * ay_z - ax_z * ay_y;
    float az_y = ax_z * ay_x - ax_x * ay_z;
    float az_z = ax_x * ay_y - ax_y * ay_x;

    // --- stage results into this warp's smem region (scattered STS: cheap) ---
    float* rp = sROT + (w * PPW + lp) * 9;
    float* xp = sXYZ + (w * PPW + lp) * 3;
    if (h == 0) {
        if (MODE == 0) {
            ((float*)sIND)[w * PPW * 2 + lp] = (float)bi; // MODE0 uses float slots
        } else {
            sIND[w * PPW + lp] = (unsigned long long)(long long)bi;
        }
        xp[0] = nx;
        xp[1] = ny;
        xp[2] = nz;
        // row-major [r][c]: col0 = ax, col1 = ay, col2 = az
        rp[0] = ax_x;
        rp[1] = ay_x;
        rp[2] = az_x;
        rp[3] = ax_y;
    } else {
        rp[4] = ay_y;
        rp[5] = az_y;
        rp[6] = ax_z;
        rp[7] = ay_z;
        rp[8] = az_z;
    }
    __syncwarp();

    // --- warp-coalesced copy-out ---
    int p0w = blockIdx.x * (TPB / 2) + w * PPW;
    int nv  = P - p0w;
    if (nv <= 0) return;
    if (nv > PPW) nv = PPW;

    float* out_xyz;
    float* out_rot;
    if (MODE == 0) {
        out_xyz = out + P;
        out_rot = out + P + 3 * (long long)P;
    } else {
        out_xyz = out + 2 * (long long)P;
        out_rot = out + 2 * (long long)P + 3 * (long long)P;
    }

    bool fast = (nv == PPW) && ((P & 3) == 0);
    if (fast) {
        // rot: 144 floats = 36 float4
        float4* gR = (float4*)(out_rot + (long long)p0w * 9);
        const float4* sR = (const float4*)(sROT + w * PPW * 9);
        gR[lane] = sR[lane];
        if (lane < 4) gR[32 + lane] = sR[32 + lane];
        // xyz: 48 floats = 12 float4
        float4* gX = (float4*)(out_xyz + (long long)p0w * 3);
        const float4* sX = (const float4*)(sXYZ + w * PPW * 3);
        if (lane < 12) gX[lane] = sX[lane];
        // indices
        if (MODE == 0) {
            float4* gI = (float4*)(out + p0w);
            const float4* sI = (const float4*)((const float*)sIND + w * PPW * 2);
            if (lane < 4) gI[lane] = sI[lane];
        } else {
            ulonglong2* gI = (ulonglong2*)((unsigned long long*)out + p0w);
            const ulonglong2* sI = (const ulonglong2*)(sIND + w * PPW);
            if (lane < 8) gI[lane] = sI[lane];
        }
    } else {
        // scalar tail: lane = local point
        if (lane < nv) {
            int pp = p0w + lane;
            const float* rs = sROT + (w * PPW + lane) * 9;
            const float* xs = sXYZ + (w * PPW + lane) * 3;
            for (int k = 0; k < 9; k++)
                out_rot[(long long)pp * 9 + k] = rs[k];
            for (int k = 0; k < 3; k++)
                out_xyz[(long long)pp * 3 + k] = xs[k];
            if (MODE == 0) {
                out[pp] = ((const float*)sIND)[w * PPW * 2 + lane];
            } else {
                ((unsigned long long*)out)[pp] = sIND[w * PPW + lane];
            }
        }
    }
}

// Host-side codebook build (fp64 libm matches numpy's float64 path).
static void np_build_codebook(NPCodebook* cb) {
    const double PHI = (sqrt(5.0) - 1.0) * 0.5;
    for (int i = 0; i < NUM_VIEW; i++) {
        double di = (double)i;
        double zi = (2.0 * di + 1.0) / (double)NUM_VIEW - 1.0;
        double r2 = 1.0 - zi * zi;
        if (r2 < 0.0) r2 = 0.0;
        double r  = sqrt(r2);
        double ang = 2.0 * di * M_PI * PHI;
        float xf = (float)(r * cos(ang));
        float yf = (float)(r * sin(ang));

        int j = i >> 1;
        int o = i & 1;
        float* fa = (float*)&cb->A[j];
        fa[0 + o] = xf;
        fa[2 + o] = yf;
    }
}

extern "C" void kernel_launch(void* const* d_in, const int* in_sizes, int n_in,
                              void* d_out, int out_size) {
    const float* normals = (const float*)d_in[0];
    const int*   idxs    = (const int*)d_in[1];
    float*       out     = (float*)d_out;

    const int B = 8;
    int P = in_sizes[1];            // B*S = 32768
    int S = P / B;                  // 4096
    int N = in_sizes[0] / (B * 3);  // 500000

    int logS = -1;
    if (S > 0 && (S & (S - 1)) == 0) {
        logS = 0;
        while ((1 << logS) < S) logS++;
    }

    NPCodebook cb;
    np_build_codebook(&cb);

    // 2 lanes per point; single kernel, one balanced wave: 147 x 448
    long long total = 2LL * P;
    int blocks = (int)((total + TPB - 1) / TPB);
    if (out_size == 14 * P) {
        np_main_kernel<1><<<blocks, TPB>>>(cb, normals, idxs, out, N, S, logS, P);
    } else {
        np_main_kernel<0><<<blocks, TPB>>>(cb, normals, idxs, out, N, S, logS, P);
    }
}